// round 4
// baseline (speedup 1.0000x reference)
#include <cuda_runtime.h>
#include <cuda_bf16.h>
#include <math.h>
#include <stdint.h>

// ---------------------------------------------------------------------------
// TensoRF_Slim: fused TensoRF feature sampling + volume rendering.
// Round 3: plain fp32 feature path (TF32 reverted); sigma/alpha chain in
// double precision so --use_fast_math cannot swap in __expf (MUFU) whose
// ~4-ulp error near 1.0 caused the 1.9e-3 mismatch via 1-exp(-tiny).
// ---------------------------------------------------------------------------

#define MAXG 300
#define GG (MAXG * MAXG)

// Device-global scratch (static allocation; no runtime allocs allowed).
__device__ float g_dplanesT[3 * GG * 8];    // (3, G*G, 8)
__device__ float g_aplanesT[3 * GG * 24];   // (3, G*G, 24)
__device__ float g_dlinesT[3 * MAXG * 8];   // (3, G, 8)
__device__ float g_alinesT[3 * MAXG * 24];  // (3, G, 24)

// ---------------------------------------------------------------------------
// Transpose (3, C, P) -> (3, P, C), tiling 32 positions per block.
// ---------------------------------------------------------------------------
template <int C>
__global__ void transpose_kernel(const float* __restrict__ in,
                                 float* __restrict__ out, int P) {
    __shared__ float tile[32][C + 1];
    int i  = blockIdx.y;          // which of 3 tensors
    int p0 = blockIdx.x * 32;
    const float* src = in + (size_t)i * C * P;
    float* dst = out + (size_t)i * P * C;

    for (int j = threadIdx.x; j < C * 32; j += blockDim.x) {
        int c = j >> 5, pp = j & 31;
        int p = p0 + pp;
        tile[pp][c] = (p < P) ? src[(size_t)c * P + p] : 0.f;
    }
    __syncthreads();
    for (int j = threadIdx.x; j < C * 32; j += blockDim.x) {
        int pp = j / C, c = j - pp * C;
        int p = p0 + pp;
        if (p < P) dst[(size_t)p * C + c] = tile[pp][c];
    }
}

// ---------------------------------------------------------------------------
// Main render kernel: one block per ray, one thread per sample.
// ---------------------------------------------------------------------------
__device__ __forceinline__ float4 f4fma(float w, float4 a, float4 acc) {
    acc.x = fmaf(w, a.x, acc.x);
    acc.y = fmaf(w, a.y, acc.y);
    acc.z = fmaf(w, a.z, acc.z);
    acc.w = fmaf(w, a.w, acc.w);
    return acc;
}

__global__ __launch_bounds__(256)
void render_kernel(const float* __restrict__ xyz_sampled,
                   const float* __restrict__ z_vals,
                   const float* __restrict__ wd,     // (1,24)
                   const float* __restrict__ wa,     // (3,72)
                   const float* __restrict__ aabb,   // (2,3)
                   float* __restrict__ out,          // (Nr,3)
                   int Ns, int G) {
    __shared__ float s_wd[24];
    __shared__ float s_wa[216];
    __shared__ float s_ab[6];
    __shared__ float s_scan[8];
    __shared__ float s_red[8 * 3];

    const int r = blockIdx.x;
    const int s = threadIdx.x;
    const int lane = s & 31;
    const int warp = s >> 5;

    if (s < 24) s_wd[s] = wd[s];
    for (int j = s; j < 216; j += blockDim.x) s_wa[j] = wa[j];
    if (s < 6) s_ab[s] = aabb[s];
    __syncthreads();

    const int idx = r * Ns + s;

    // normalize point into [-1, 1]
    float p[3];
#pragma unroll
    for (int k = 0; k < 3; k++) {
        float inv = 2.0f / (s_ab[3 + k] - s_ab[k]);
        p[k] = (xyz_sampled[idx * 3 + k] - s_ab[k]) * inv - 1.0f;
    }

    // per-axis grid coords
    int i0[3], i1[3];
    float fr[3];
#pragma unroll
    for (int k = 0; k < 3; k++) {
        float u  = (p[k] + 1.0f) * 0.5f * (float)(G - 1);
        float uf = floorf(u);
        fr[k] = u - uf;
        int a0 = (int)uf;
        a0 = max(0, min(a0, G - 1));
        i0[k] = a0;
        i1[k] = min(a0 + 1, G - 1);
    }

    const int mat_a[3] = {0, 0, 1};
    const int mat_b[3] = {1, 2, 2};
    const int vec_m[3] = {2, 1, 0};

    // ---------------- density ----------------
    float sigma_feat = 0.0f;
#pragma unroll
    for (int i = 0; i < 3; i++) {
        int xa = mat_a[i], yb = mat_b[i], vv = vec_m[i];
        int x0 = i0[xa], x1 = i1[xa], y0 = i0[yb], y1 = i1[yb];
        float wx = fr[xa], wy = fr[yb];
        float w00 = (1.f - wx) * (1.f - wy);
        float w01 = wx * (1.f - wy);
        float w10 = (1.f - wx) * wy;
        float w11 = wx * wy;

        const float4* gp = reinterpret_cast<const float4*>(g_dplanesT + (size_t)i * GG * 8);
        int o00 = (y0 * G + x0) * 2, o01 = (y0 * G + x1) * 2;
        int o10 = (y1 * G + x0) * 2, o11 = (y1 * G + x1) * 2;

        float4 pa = make_float4(0, 0, 0, 0), pb = make_float4(0, 0, 0, 0);
        pa = f4fma(w00, gp[o00], pa);   pb = f4fma(w00, gp[o00 + 1], pb);
        pa = f4fma(w01, gp[o01], pa);   pb = f4fma(w01, gp[o01 + 1], pb);
        pa = f4fma(w10, gp[o10], pa);   pb = f4fma(w10, gp[o10 + 1], pb);
        pa = f4fma(w11, gp[o11], pa);   pb = f4fma(w11, gp[o11 + 1], pb);

        const float4* gl = reinterpret_cast<const float4*>(g_dlinesT + (size_t)i * MAXG * 8);
        int t0 = i0[vv], t1 = i1[vv];
        float wt = fr[vv];
        float4 la = make_float4(0, 0, 0, 0), lb = make_float4(0, 0, 0, 0);
        la = f4fma(1.f - wt, gl[t0 * 2], la);     lb = f4fma(1.f - wt, gl[t0 * 2 + 1], lb);
        la = f4fma(wt,       gl[t1 * 2], la);     lb = f4fma(wt,       gl[t1 * 2 + 1], lb);

        const float* w8 = &s_wd[i * 8];
        sigma_feat += w8[0] * (pa.x * la.x) + w8[1] * (pa.y * la.y) +
                      w8[2] * (pa.z * la.z) + w8[3] * (pa.w * la.w) +
                      w8[4] * (pb.x * lb.x) + w8[5] * (pb.y * lb.y) +
                      w8[6] * (pb.z * lb.z) + w8[7] * (pb.w * lb.w);
    }

    // dists (fp32, exact subtraction semantics)
    float z_s = z_vals[idx];
    float dist;
    if (s < Ns - 1) dist = z_vals[idx + 1] - z_s;
    else            dist = z_s - z_vals[idx - 1];
    float dist25 = dist * 25.0f;

    // sigma + alpha in DOUBLE precision: immune to --use_fast_math's
    // expf->__expf rewrite. alpha = 1 - exp(-tiny) is quantized at
    // ulp(1.0)=6e-8 (~0.3% of alpha), so the exp must be accurate.
    double xs  = (double)sigma_feat - 10.0;
    double sig = fmax(xs, 0.0) + log1p(exp(-fabs(xs)));
    double e   = exp(-sig * (double)dist25);
    float alpha = 1.0f - (float)e;

    // ---------------- appearance (rgb) ----------------
    float rgb0 = 0.f, rgb1 = 0.f, rgb2 = 0.f;
#pragma unroll
    for (int i = 0; i < 3; i++) {
        int xa = mat_a[i], yb = mat_b[i], vv = vec_m[i];
        int x0 = i0[xa], x1 = i1[xa], y0 = i0[yb], y1 = i1[yb];
        float wx = fr[xa], wy = fr[yb];
        float w00 = (1.f - wx) * (1.f - wy);
        float w01 = wx * (1.f - wy);
        float w10 = (1.f - wx) * wy;
        float w11 = wx * wy;

        const float4* gp = reinterpret_cast<const float4*>(g_aplanesT + (size_t)i * GG * 24);
        int o00 = (y0 * G + x0) * 6, o01 = (y0 * G + x1) * 6;
        int o10 = (y1 * G + x0) * 6, o11 = (y1 * G + x1) * 6;

        const float4* gl = reinterpret_cast<const float4*>(g_alinesT + (size_t)i * MAXG * 24);
        int t0 = i0[vv] * 6, t1 = i1[vv] * 6;
        float wt = fr[vv];

#pragma unroll
        for (int g = 0; g < 6; g++) {
            float4 f = make_float4(0, 0, 0, 0);
            f = f4fma(w00, gp[o00 + g], f);
            f = f4fma(w01, gp[o01 + g], f);
            f = f4fma(w10, gp[o10 + g], f);
            f = f4fma(w11, gp[o11 + g], f);
            float4 l = make_float4(0, 0, 0, 0);
            l = f4fma(1.f - wt, gl[t0 + g], l);
            l = f4fma(wt,       gl[t1 + g], l);
            float fx = f.x * l.x, fy = f.y * l.y, fz = f.z * l.z, fw = f.w * l.w;
            int jb = i * 24 + g * 4;
            rgb0 += s_wa[jb + 0] * fx + s_wa[jb + 1] * fy + s_wa[jb + 2] * fz + s_wa[jb + 3] * fw;
            rgb1 += s_wa[72 + jb + 0] * fx + s_wa[72 + jb + 1] * fy + s_wa[72 + jb + 2] * fz + s_wa[72 + jb + 3] * fw;
            rgb2 += s_wa[144 + jb + 0] * fx + s_wa[144 + jb + 1] * fy + s_wa[144 + jb + 2] * fz + s_wa[144 + jb + 3] * fw;
        }
    }

    // ---------------- transmittance scan (block-wide exclusive product) ----
    float m = 1.0f - alpha + 1e-10f;
    float v = m;
#pragma unroll
    for (int o = 1; o < 32; o <<= 1) {
        float t = __shfl_up_sync(0xFFFFFFFFu, v, o);
        if (lane >= o) v *= t;
    }
    float excl = __shfl_up_sync(0xFFFFFFFFu, v, 1);
    if (lane == 0) excl = 1.0f;
    if (lane == 31) s_scan[warp] = v;
    __syncthreads();
    float pre = 1.0f;
    for (int w = 0; w < warp; w++) pre *= s_scan[w];
    float T = pre * excl;
    float wgt = alpha * T;

    // ---------------- weighted rgb reduce ----------------
    float a0 = wgt * rgb0, a1 = wgt * rgb1, a2 = wgt * rgb2;
#pragma unroll
    for (int o = 16; o > 0; o >>= 1) {
        a0 += __shfl_xor_sync(0xFFFFFFFFu, a0, o);
        a1 += __shfl_xor_sync(0xFFFFFFFFu, a1, o);
        a2 += __shfl_xor_sync(0xFFFFFFFFu, a2, o);
    }
    if (lane == 0) {
        s_red[warp * 3 + 0] = a0;
        s_red[warp * 3 + 1] = a1;
        s_red[warp * 3 + 2] = a2;
    }
    __syncthreads();
    if (s == 0) {
        float o0 = 0.f, o1 = 0.f, o2 = 0.f;
        int nw = blockDim.x >> 5;
        for (int w = 0; w < nw; w++) {
            o0 += s_red[w * 3 + 0];
            o1 += s_red[w * 3 + 1];
            o2 += s_red[w * 3 + 2];
        }
        out[r * 3 + 0] = o0;
        out[r * 3 + 1] = o1;
        out[r * 3 + 2] = o2;
    }
}

// ---------------------------------------------------------------------------
// Launch
// ---------------------------------------------------------------------------
extern "C" void kernel_launch(void* const* d_in, const int* in_sizes, int n_in,
                              void* d_out, int out_size) {
    const float* xyz_sampled    = (const float*)d_in[0];
    // d_in[1] = viewdirs (unused)
    const float* z_vals         = (const float*)d_in[2];
    const float* density_planes = (const float*)d_in[3];
    const float* density_lines  = (const float*)d_in[4];
    const float* app_planes     = (const float*)d_in[5];
    const float* app_lines      = (const float*)d_in[6];
    const float* density_bw     = (const float*)d_in[7];
    const float* app_bw         = (const float*)d_in[8];
    const float* aabb           = (const float*)d_in[9];
    float* out = (float*)d_out;

    int Nr = in_sizes[1] / 3;
    int Ns = in_sizes[2] / Nr;
    int g2 = in_sizes[3] / (3 * 8);
    int G  = (int)(sqrtf((float)g2) + 0.5f);

    float *dpT, *apT, *dlT, *alT;
    cudaGetSymbolAddress((void**)&dpT, g_dplanesT);
    cudaGetSymbolAddress((void**)&apT, g_aplanesT);
    cudaGetSymbolAddress((void**)&dlT, g_dlinesT);
    cudaGetSymbolAddress((void**)&alT, g_alinesT);

    int P = G * G;
    {
        dim3 grid((P + 31) / 32, 3);
        transpose_kernel<8><<<grid, 256>>>(density_planes, dpT, P);
        transpose_kernel<24><<<grid, 256>>>(app_planes, apT, P);
    }
    {
        dim3 grid((G + 31) / 32, 3);
        transpose_kernel<8><<<grid, 64>>>(density_lines, dlT, G);
        transpose_kernel<24><<<grid, 192>>>(app_lines, alT, G);
    }

    render_kernel<<<Nr, Ns>>>(xyz_sampled, z_vals, density_bw, app_bw, aabb,
                              out, Ns, G);
}

// round 5
// speedup vs baseline: 1.8136x; 1.8136x over previous
#include <cuda_runtime.h>
#include <cuda_bf16.h>
#include <cuda_fp16.h>
#include <math.h>
#include <stdint.h>

// ---------------------------------------------------------------------------
// TensoRF_Slim: fused TensoRF feature sampling + volume rendering.
// Round 4 (perf): planes/lines compressed to fp16 channel-last during the
// transpose pass. Halves the divergent-LDG count (144 -> 72 per point) on a
// workload shown to be L1tex-wavefront-bound. Alpha chain stays fp64
// (fast-math-immune accurate exp) -- that was the R3 correctness fix.
// ---------------------------------------------------------------------------

#define MAXG 300
#define GG (MAXG * MAXG)

// Device-global scratch (static allocation; no runtime allocs allowed).
// 16B-aligned for uint4 vector loads.
__device__ __align__(16) __half g_dplanesH[3 * GG * 8];    // (3, G*G, 8)
__device__ __align__(16) __half g_aplanesH[3 * GG * 24];   // (3, G*G, 24)
__device__ __align__(16) __half g_dlinesH[3 * MAXG * 8];   // (3, G, 8)
__device__ __align__(16) __half g_alinesH[3 * MAXG * 24];  // (3, G, 24)

// ---------------------------------------------------------------------------
// Transpose (3, C, P) fp32 -> (3, P, C) fp16, tiling 32 positions per block.
// ---------------------------------------------------------------------------
template <int C>
__global__ void transpose_kernel(const float* __restrict__ in,
                                 __half* __restrict__ out, int P) {
    __shared__ float tile[32][C + 1];
    int i  = blockIdx.y;          // which of 3 tensors
    int p0 = blockIdx.x * 32;
    const float* src = in + (size_t)i * C * P;
    __half* dst = out + (size_t)i * P * C;

    for (int j = threadIdx.x; j < C * 32; j += blockDim.x) {
        int c = j >> 5, pp = j & 31;
        int p = p0 + pp;
        tile[pp][c] = (p < P) ? src[(size_t)c * P + p] : 0.f;
    }
    __syncthreads();
    for (int j = threadIdx.x; j < C * 32; j += blockDim.x) {
        int pp = j / C, c = j - pp * C;
        int p = p0 + pp;
        if (p < P) dst[(size_t)p * C + c] = __float2half_rn(tile[pp][c]);
    }
}

// ---------------------------------------------------------------------------
// fp16 vector helpers
// ---------------------------------------------------------------------------
// Accumulate w * (8 halves in a uint4) into acc[8].
__device__ __forceinline__ void acc8(float* acc, float w, uint4 v) {
    const __half2* h = reinterpret_cast<const __half2*>(&v);
#pragma unroll
    for (int j = 0; j < 4; j++) {
        float2 f = __half22float2(h[j]);
        acc[2 * j + 0] = fmaf(w, f.x, acc[2 * j + 0]);
        acc[2 * j + 1] = fmaf(w, f.y, acc[2 * j + 1]);
    }
}

// ---------------------------------------------------------------------------
// Main render kernel: one block per ray, one thread per sample.
// ---------------------------------------------------------------------------
__global__ __launch_bounds__(256)
void render_kernel(const float* __restrict__ xyz_sampled,
                   const float* __restrict__ z_vals,
                   const float* __restrict__ wd,     // (1,24)
                   const float* __restrict__ wa,     // (3,72)
                   const float* __restrict__ aabb,   // (2,3)
                   float* __restrict__ out,          // (Nr,3)
                   int Ns, int G) {
    __shared__ float s_wd[24];
    __shared__ float s_wa[216];
    __shared__ float s_ab[6];
    __shared__ float s_scan[8];
    __shared__ float s_red[8 * 3];

    const int r = blockIdx.x;
    const int s = threadIdx.x;
    const int lane = s & 31;
    const int warp = s >> 5;

    if (s < 24) s_wd[s] = wd[s];
    for (int j = s; j < 216; j += blockDim.x) s_wa[j] = wa[j];
    if (s < 6) s_ab[s] = aabb[s];
    __syncthreads();

    const int idx = r * Ns + s;

    // normalize point into [-1, 1]
    float p[3];
#pragma unroll
    for (int k = 0; k < 3; k++) {
        float inv = 2.0f / (s_ab[3 + k] - s_ab[k]);
        p[k] = (xyz_sampled[idx * 3 + k] - s_ab[k]) * inv - 1.0f;
    }

    // per-axis grid coords
    int i0[3], i1[3];
    float fr[3];
#pragma unroll
    for (int k = 0; k < 3; k++) {
        float u  = (p[k] + 1.0f) * 0.5f * (float)(G - 1);
        float uf = floorf(u);
        fr[k] = u - uf;
        int a0 = (int)uf;
        a0 = max(0, min(a0, G - 1));
        i0[k] = a0;
        i1[k] = min(a0 + 1, G - 1);
    }

    const int mat_a[3] = {0, 0, 1};
    const int mat_b[3] = {1, 2, 2};
    const int vec_m[3] = {2, 1, 0};

    // ---------------- density ----------------
    float sigma_feat = 0.0f;
#pragma unroll
    for (int i = 0; i < 3; i++) {
        int xa = mat_a[i], yb = mat_b[i], vv = vec_m[i];
        int x0 = i0[xa], x1 = i1[xa], y0 = i0[yb], y1 = i1[yb];
        float wx = fr[xa], wy = fr[yb];
        float w00 = (1.f - wx) * (1.f - wy);
        float w01 = wx * (1.f - wy);
        float w10 = (1.f - wx) * wy;
        float w11 = wx * wy;

        // plane texel = 8 halves = one uint4
        const uint4* gp = reinterpret_cast<const uint4*>(g_dplanesH + (size_t)i * GG * 8);
        float pf[8];
#pragma unroll
        for (int c = 0; c < 8; c++) pf[c] = 0.f;
        acc8(pf, w00, gp[y0 * G + x0]);
        acc8(pf, w01, gp[y0 * G + x1]);
        acc8(pf, w10, gp[y1 * G + x0]);
        acc8(pf, w11, gp[y1 * G + x1]);

        const uint4* gl = reinterpret_cast<const uint4*>(g_dlinesH + (size_t)i * MAXG * 8);
        int t0 = i0[vv], t1 = i1[vv];
        float wt = fr[vv];
        float lf[8];
#pragma unroll
        for (int c = 0; c < 8; c++) lf[c] = 0.f;
        acc8(lf, 1.f - wt, gl[t0]);
        acc8(lf, wt,       gl[t1]);

        const float* w8 = &s_wd[i * 8];
#pragma unroll
        for (int c = 0; c < 8; c++)
            sigma_feat += w8[c] * (pf[c] * lf[c]);
    }

    // dists (fp32, exact subtraction semantics)
    float z_s = z_vals[idx];
    float dist;
    if (s < Ns - 1) dist = z_vals[idx + 1] - z_s;
    else            dist = z_s - z_vals[idx - 1];
    float dist25 = dist * 25.0f;

    // sigma + alpha in DOUBLE precision: immune to --use_fast_math's
    // expf->__expf rewrite (R3 correctness fix -- do not touch).
    double xs  = (double)sigma_feat - 10.0;
    double sig = fmax(xs, 0.0) + log1p(exp(-fabs(xs)));
    double e   = exp(-sig * (double)dist25);
    float alpha = 1.0f - (float)e;

    // ---------------- appearance (rgb) ----------------
    float rgb0 = 0.f, rgb1 = 0.f, rgb2 = 0.f;
#pragma unroll
    for (int i = 0; i < 3; i++) {
        int xa = mat_a[i], yb = mat_b[i], vv = vec_m[i];
        int x0 = i0[xa], x1 = i1[xa], y0 = i0[yb], y1 = i1[yb];
        float wx = fr[xa], wy = fr[yb];
        float w00 = (1.f - wx) * (1.f - wy);
        float w01 = wx * (1.f - wy);
        float w10 = (1.f - wx) * wy;
        float w11 = wx * wy;

        // app texel = 24 halves = 3 uint4 (48B, 16B-aligned)
        const uint4* gp = reinterpret_cast<const uint4*>(g_aplanesH + (size_t)i * GG * 24);
        int o00 = (y0 * G + x0) * 3, o01 = (y0 * G + x1) * 3;
        int o10 = (y1 * G + x0) * 3, o11 = (y1 * G + x1) * 3;

        const uint4* gl = reinterpret_cast<const uint4*>(g_alinesH + (size_t)i * MAXG * 24);
        int t0 = i0[vv] * 3, t1 = i1[vv] * 3;
        float wt = fr[vv];

        float f[24], l[24];
#pragma unroll
        for (int c = 0; c < 24; c++) { f[c] = 0.f; l[c] = 0.f; }
#pragma unroll
        for (int q = 0; q < 3; q++) {
            acc8(f + 8 * q, w00, gp[o00 + q]);
            acc8(f + 8 * q, w01, gp[o01 + q]);
            acc8(f + 8 * q, w10, gp[o10 + q]);
            acc8(f + 8 * q, w11, gp[o11 + q]);
            acc8(l + 8 * q, 1.f - wt, gl[t0 + q]);
            acc8(l + 8 * q, wt,       gl[t1 + q]);
        }

        const float* wrow = &s_wa[i * 24];
#pragma unroll
        for (int c = 0; c < 24; c++) {
            float fl = f[c] * l[c];
            rgb0 = fmaf(wrow[c],       fl, rgb0);
            rgb1 = fmaf(wrow[72 + c],  fl, rgb1);
            rgb2 = fmaf(wrow[144 + c], fl, rgb2);
        }
    }

    // ---------------- transmittance scan (block-wide exclusive product) ----
    float m = 1.0f - alpha + 1e-10f;
    float v = m;
#pragma unroll
    for (int o = 1; o < 32; o <<= 1) {
        float t = __shfl_up_sync(0xFFFFFFFFu, v, o);
        if (lane >= o) v *= t;
    }
    float excl = __shfl_up_sync(0xFFFFFFFFu, v, 1);
    if (lane == 0) excl = 1.0f;
    if (lane == 31) s_scan[warp] = v;
    __syncthreads();
    float pre = 1.0f;
    for (int w = 0; w < warp; w++) pre *= s_scan[w];
    float T = pre * excl;
    float wgt = alpha * T;

    // ---------------- weighted rgb reduce ----------------
    float a0 = wgt * rgb0, a1 = wgt * rgb1, a2 = wgt * rgb2;
#pragma unroll
    for (int o = 16; o > 0; o >>= 1) {
        a0 += __shfl_xor_sync(0xFFFFFFFFu, a0, o);
        a1 += __shfl_xor_sync(0xFFFFFFFFu, a1, o);
        a2 += __shfl_xor_sync(0xFFFFFFFFu, a2, o);
    }
    if (lane == 0) {
        s_red[warp * 3 + 0] = a0;
        s_red[warp * 3 + 1] = a1;
        s_red[warp * 3 + 2] = a2;
    }
    __syncthreads();
    if (s == 0) {
        float o0 = 0.f, o1 = 0.f, o2 = 0.f;
        int nw = blockDim.x >> 5;
        for (int w = 0; w < nw; w++) {
            o0 += s_red[w * 3 + 0];
            o1 += s_red[w * 3 + 1];
            o2 += s_red[w * 3 + 2];
        }
        out[r * 3 + 0] = o0;
        out[r * 3 + 1] = o1;
        out[r * 3 + 2] = o2;
    }
}

// ---------------------------------------------------------------------------
// Launch
// ---------------------------------------------------------------------------
extern "C" void kernel_launch(void* const* d_in, const int* in_sizes, int n_in,
                              void* d_out, int out_size) {
    const float* xyz_sampled    = (const float*)d_in[0];
    // d_in[1] = viewdirs (unused)
    const float* z_vals         = (const float*)d_in[2];
    const float* density_planes = (const float*)d_in[3];
    const float* density_lines  = (const float*)d_in[4];
    const float* app_planes     = (const float*)d_in[5];
    const float* app_lines      = (const float*)d_in[6];
    const float* density_bw     = (const float*)d_in[7];
    const float* app_bw         = (const float*)d_in[8];
    const float* aabb           = (const float*)d_in[9];
    float* out = (float*)d_out;

    int Nr = in_sizes[1] / 3;
    int Ns = in_sizes[2] / Nr;
    int g2 = in_sizes[3] / (3 * 8);
    int G  = (int)(sqrtf((float)g2) + 0.5f);

    __half *dpH, *apH, *dlH, *alH;
    cudaGetSymbolAddress((void**)&dpH, g_dplanesH);
    cudaGetSymbolAddress((void**)&apH, g_aplanesH);
    cudaGetSymbolAddress((void**)&dlH, g_dlinesH);
    cudaGetSymbolAddress((void**)&alH, g_alinesH);

    int P = G * G;
    {
        dim3 grid((P + 31) / 32, 3);
        transpose_kernel<8><<<grid, 256>>>(density_planes, dpH, P);
        transpose_kernel<24><<<grid, 256>>>(app_planes, apH, P);
    }
    {
        dim3 grid((G + 31) / 32, 3);
        transpose_kernel<8><<<grid, 64>>>(density_lines, dlH, G);
        transpose_kernel<24><<<grid, 192>>>(app_lines, alH, G);
    }

    render_kernel<<<Nr, Ns>>>(xyz_sampled, z_vals, density_bw, app_bw, aabb,
                              out, Ns, G);
}